// round 14
// baseline (speedup 1.0000x reference)
#include <cuda_runtime.h>
#include <cuda_fp16.h>
#include <cstddef>
#include <cstdint>

// ---------------- Problem constants (fixed by the reference) ----------------
#define N_NODES 50000
#define E_EDGES 800000
#define NFEAT   512
#define NH      256
#define NL      4
#define EVO     1024

// ---------------- Device-global scratch (no allocations allowed) ------------
__device__ __half g_local0[(size_t)N_NODES * NH];         // relu(x @ fc0), fp16
__device__ __half g_h[(size_t)N_NODES * NH];              // conv dense transform, fp16
__device__ __half g_layers[(size_t)N_NODES * NL * NH];    // spmm outputs, fp16
__device__ __half g_glob[(size_t)N_NODES * NH];           // relu(evo @ fc1), fp16
__device__ __half g_local2[(size_t)N_NODES * NH];         // relu(layers @ fc2), fp16

// All weights fp16, pre-transposed W^T [256][K] (k contiguous):
//  fc0 @0 (256x512), conv @131072 (4x256x256), fc1 @393216 (256x1024),
//  fc2 @655360 (256x1024), fc3 @917504 (256x512)
__device__ __half g_wth[1048576];

__device__ int   g_counts[N_NODES];
__device__ int   g_rowptr[N_NODES + 1];
__device__ int   g_cursor[N_NODES];
__device__ int   g_colidx[E_EDGES];
__device__ float g_vals[E_EDGES];

// ---------------- Weight prep: transpose + round to fp16 ---------------------
__global__ __launch_bounds__(256) void k_prep_w(
    const float* __restrict__ fc0w, const float* __restrict__ convw,
    const float* __restrict__ fc1w, const float* __restrict__ fc2w,
    const float* __restrict__ fc3w)
{
    const int i = blockIdx.x * 256 + threadIdx.x;         // 4096 x 256 = 1048576
    float v;
    if (i < 131072)      { int n = i >> 9, k = i & 511;   v = fc0w[k * 256 + n]; }
    else if (i < 393216) { int j = i - 131072; int m = j >> 16; int r = j & 65535;
                           int n = r >> 8, k = r & 255;   v = convw[m * 65536 + k * 256 + n]; }
    else if (i < 655360) { int j = i - 393216; int n = j >> 10, k = j & 1023;
                           v = fc1w[k * 256 + n]; }
    else if (i < 917504) { int j = i - 655360; int n = j >> 10, k = j & 1023;
                           v = fc2w[k * 256 + n]; }
    else                 { int j = i - 917504; int n = j >> 9, k = j & 511;
                           v = fc3w[k * 256 + n]; }
    g_wth[i] = __float2half_rn(v);
}

// ---------------- CSR build kernels ----------------------------------------
__global__ void k_zero_counts() {
    int i = blockIdx.x * blockDim.x + threadIdx.x;
    if (i < N_NODES) g_counts[i] = 0;
}

__global__ void k_hist(const int* __restrict__ dst) {
    int e = blockIdx.x * blockDim.x + threadIdx.x;
    if (e < E_EDGES) atomicAdd(&g_counts[dst[e]], 1);
}

__global__ void k_scan() {
    __shared__ int warp_sums[32];
    __shared__ int s_carry;
    const int t = threadIdx.x, lane = t & 31, wid = t >> 5;
    if (t == 0) s_carry = 0;
    __syncthreads();
    for (int base = 0; base < N_NODES; base += 1024) {
        const int i = base + t;
        const int v = (i < N_NODES) ? g_counts[i] : 0;
        int x = v;
#pragma unroll
        for (int d = 1; d < 32; d <<= 1) {
            int y = __shfl_up_sync(0xFFFFFFFFu, x, d);
            if (lane >= d) x += y;
        }
        if (lane == 31) warp_sums[wid] = x;
        __syncthreads();
        if (wid == 0) {
            int w = warp_sums[lane];
            int ws = w;
#pragma unroll
            for (int d = 1; d < 32; d <<= 1) {
                int y = __shfl_up_sync(0xFFFFFFFFu, ws, d);
                if (lane >= d) ws += y;
            }
            warp_sums[lane] = ws - w;
        }
        __syncthreads();
        const int ex = x - v + warp_sums[wid];
        const int carry = s_carry;
        if (i < N_NODES) {
            g_rowptr[i] = carry + ex;
            g_cursor[i] = carry + ex;
        }
        __syncthreads();
        if (t == 1023) s_carry = carry + ex + v;
        __syncthreads();
    }
    if (threadIdx.x == 0) g_rowptr[N_NODES] = s_carry;
}

__global__ void k_scatter(const int* __restrict__ src, const int* __restrict__ dst,
                          const float* __restrict__ w) {
    int e = blockIdx.x * blockDim.x + threadIdx.x;
    if (e < E_EDGES) {
        int d = dst[e];
        int pos = atomicAdd(&g_cursor[d], 1);
        g_colidx[pos] = src[e];
        g_vals[pos]   = w[e];
    }
}

// ---------------- common asm helpers ----------------------------------------
__device__ __forceinline__ void ldsm4(uint32_t& r0, uint32_t& r1, uint32_t& r2, uint32_t& r3,
                                      uint32_t addr) {
    asm volatile("ldmatrix.sync.aligned.m8n8.x4.shared.b16 {%0,%1,%2,%3}, [%4];"
                 : "=r"(r0), "=r"(r1), "=r"(r2), "=r"(r3) : "r"(addr));
}

__device__ __forceinline__ void cp16(uint32_t dst_s, const void* src, bool valid) {
    int sz = valid ? 16 : 0;
    asm volatile("cp.async.cg.shared.global [%0], [%1], 16, %2;\n"
                 :: "r"(dst_s), "l"(src), "r"(sz));
}

__device__ __forceinline__ void mma_f16(float* d, const uint32_t* a, const uint32_t* b) {
    asm volatile(
        "mma.sync.aligned.m16n8k16.row.col.f32.f16.f16.f32 "
        "{%0,%1,%2,%3}, {%4,%5,%6,%7}, {%8,%9}, {%0,%1,%2,%3};\n"
        : "+f"(d[0]), "+f"(d[1]), "+f"(d[2]), "+f"(d[3])
        : "r"(a[0]), "r"(a[1]), "r"(a[2]), "r"(a[3]), "r"(b[0]), "r"(b[1]));
}

// ============================================================================
// FP16 GEMM (fp16 A + fp16 B, mma.m16n8k16, fp32 accum), BK=64, 3 stages.
// ============================================================================
#define G16_BK 64
#define G16_PA 72                       // halves; 144B stride, conflict-free
#define G16_STG_H (128 * G16_PA * 2)    // halves per stage (A + B) = 18432
#define G16_SMEM (3 * G16_STG_H * 2)    // bytes = 110592

template <bool RELU, bool CONCAT, bool OUT_HALF>
__global__ __launch_bounds__(256, 2) void h16gemm(
    const __half* __restrict__ A, int lda, int K,
    const __half* __restrict__ A2,          // CONCAT: second A at k>=256 (lda=256)
    const __half* __restrict__ Bt,          // [256][K] fp16, k contiguous
    const float* __restrict__ bias,
    void* __restrict__ Cv, int ldc, int M)
{
    constexpr int PA = G16_PA, BK = G16_BK;
    extern __shared__ __half dynsmem_h[];

    const int t    = threadIdx.x;
    const int lane = t & 31;
    const int warp = t >> 5;
    const int row0 = blockIdx.y * 128;
    const int col0 = blockIdx.x * 128;
    const int m0w  = (warp & 1) * 64;
    const int n0w  = (warp >> 1) * 32;
    const int g    = lane >> 2;
    const int q    = lane & 3;

    const uint32_t smem_u = (uint32_t)__cvta_generic_to_shared(dynsmem_h);

    float acc[4][4][4];
#pragma unroll
    for (int mi = 0; mi < 4; mi++)
#pragma unroll
        for (int ni = 0; ni < 4; ni++)
#pragma unroll
            for (int r = 0; r < 4; r++) acc[mi][ni][r] = 0.f;

    const int lr0 = t >> 3;
    const int lhc = (t & 7) * 8;

    const int a_lm = ((m0w + (lane & 15)) * PA + (lane >> 4) * 8) * 2;
    const int b_row = n0w + (lane & 7) + ((lane >> 4) & 1) * 8;
    const int b_lm  = (b_row * PA + ((lane >> 3) & 1) * 8) * 2;

    auto issue = [&](int buf, int stage_idx) {
        const int k0 = stage_idx * BK;
        const uint32_t as_u = smem_u + (uint32_t)(buf * G16_STG_H) * 2u;
        const uint32_t bs_u = as_u + (uint32_t)(128 * PA) * 2u;
        const __half* Asel = A;
        int kbase = k0;
        if (CONCAT && k0 >= 256) { Asel = A2; kbase = k0 - 256; }
#pragma unroll
        for (int i = 0; i < 4; i++) {
            const int row = lr0 + i * 32;
            const bool valid = (row0 + row) < M;
            const int rclamp = valid ? (row0 + row) : (M - 1);
            cp16(as_u + (uint32_t)(row * PA + lhc) * 2u,
                 Asel + (size_t)rclamp * lda + kbase + lhc, valid);
        }
#pragma unroll
        for (int i = 0; i < 4; i++) {
            const int row = lr0 + i * 32;
            cp16(bs_u + (uint32_t)(row * PA + lhc) * 2u,
                 Bt + (size_t)(col0 + row) * K + k0 + lhc, true);
        }
    };

    auto compute = [&](int buf) {
        const uint32_t as_u = smem_u + (uint32_t)(buf * G16_STG_H) * 2u;
        const uint32_t bs_u = as_u + (uint32_t)(128 * PA) * 2u;
#pragma unroll
        for (int kk = 0; kk < BK; kk += 16) {
            uint32_t a[4][4], b[4][2];
#pragma unroll
            for (int mi = 0; mi < 4; mi++)
                ldsm4(a[mi][0], a[mi][1], a[mi][2], a[mi][3],
                      as_u + (uint32_t)(a_lm + (mi * 16 * PA + kk) * 2));
#pragma unroll
            for (int p = 0; p < 2; p++) {
                uint32_t r0, r1, r2, r3;
                ldsm4(r0, r1, r2, r3,
                      bs_u + (uint32_t)(b_lm + (p * 16 * PA + kk) * 2));
                b[p * 2 + 0][0] = r0; b[p * 2 + 0][1] = r1;
                b[p * 2 + 1][0] = r2; b[p * 2 + 1][1] = r3;
            }
#pragma unroll
            for (int mi = 0; mi < 4; mi++)
#pragma unroll
                for (int ni = 0; ni < 4; ni++)
                    mma_f16(acc[mi][ni], a[mi], b[ni]);
        }
    };

    const int nk = K / BK;
#pragma unroll
    for (int s = 0; s < 2; s++) {
        if (s < nk) issue(s, s);
        asm volatile("cp.async.commit_group;\n");
    }
    for (int it = 0; it < nk; it++) {
        asm volatile("cp.async.wait_group 1;\n");
        __syncthreads();
        const int nxt = it + 2;
        if (nxt < nk) issue(nxt % 3, nxt);
        asm volatile("cp.async.commit_group;\n");
        compute(it % 3);
    }

#pragma unroll
    for (int mi = 0; mi < 4; mi++) {
        const int r0 = row0 + m0w + mi * 16 + g;
        const int r1 = r0 + 8;
#pragma unroll
        for (int ni = 0; ni < 4; ni++) {
            const int c = col0 + n0w + ni * 8 + q * 2;
            const float bx = bias ? bias[c] : 0.f;
            const float by = bias ? bias[c + 1] : 0.f;
#pragma unroll
            for (int half = 0; half < 2; half++) {
                const int r = half ? r1 : r0;
                if (r < M) {
                    float vx = acc[mi][ni][half * 2 + 0] + bx;
                    float vy = acc[mi][ni][half * 2 + 1] + by;
                    if (RELU) { vx = fmaxf(vx, 0.f); vy = fmaxf(vy, 0.f); }
                    if (OUT_HALF) {
                        *(__half2*)((__half*)Cv + (size_t)r * ldc + c) =
                            __floats2half2_rn(vx, vy);
                    } else {
                        *(float2*)((float*)Cv + (size_t)r * ldc + c) =
                            make_float2(vx, vy);
                    }
                }
            }
        }
    }
}

// ============================================================================
// FP16 GEMM with fp32 A read directly from gmem (fc0/fc1): BK=32, 3 stages.
// A smem fp32 [m][k] stride 36 floats; B smem fp16 [n][k] stride 40 halves.
// A-frags: LDS.64 of 2 consecutive fp32 + cvt.rn.f16x2 -> packed halves.
// m16n8k16 A frag lane(g,q): a0=(g, 2q..2q+1), a1=(g+8,..), a2=(g, 8+2q..),
// a3=(g+8, 8+2q..) -- pairs are k-consecutive, so float2 @ (row, kk+2q) works.
// ============================================================================
#define GCA_BK 32
#define GCA_PAF 36                        // A stride in floats
#define GCA_PBH 40                        // B stride in halves
#define GCA_STG_B (128 * GCA_PAF * 4 + 128 * GCA_PBH * 2)   // 18432+10240=28672
#define GCA_SMEM (3 * GCA_STG_B)                            // 86016

__global__ __launch_bounds__(256, 2) void h16gemm_cvtA(
    const float* __restrict__ A, int lda, int K,
    const __half* __restrict__ Bt,          // [256][K] fp16, k contiguous
    const float* __restrict__ bias,
    __half* __restrict__ C, int ldc, int M) // relu + fp16 out
{
    constexpr int BK = GCA_BK, PAF = GCA_PAF, PBH = GCA_PBH;
    extern __shared__ char dynsmem_c[];

    const int t    = threadIdx.x;
    const int lane = t & 31;
    const int warp = t >> 5;
    const int row0 = blockIdx.y * 128;
    const int col0 = blockIdx.x * 128;
    const int m0w  = (warp & 1) * 64;
    const int n0w  = (warp >> 1) * 32;
    const int g    = lane >> 2;
    const int q    = lane & 3;

    const uint32_t smem_u = (uint32_t)__cvta_generic_to_shared(dynsmem_c);

    float acc[4][4][4];
#pragma unroll
    for (int mi = 0; mi < 4; mi++)
#pragma unroll
        for (int ni = 0; ni < 4; ni++)
#pragma unroll
            for (int r = 0; r < 4; r++) acc[mi][ni][r] = 0.f;

    // A loader (fp32, 128x32): 1024 chunks of 16B, 4/thread
    const int ar0 = t >> 3;
    const int akq = (t & 7) * 4;
    // B loader (fp16, 128x32): 512 chunks of 16B, 2/thread
    const int br0 = t >> 2;
    const int bhc = (t & 3) * 8;

    // B ldmatrix per-lane offset (same pattern as proven R11 BK=32 path)
    const int ts = lane >> 3, rowin = lane & 7;
    const int b_lm = ((n0w + (ts >> 1) * 8 + rowin) * PBH + (ts & 1) * 8) * 2;

    auto issue = [&](int buf, int stage_idx) {
        const int k0 = stage_idx * BK;
        const uint32_t as_u = smem_u + (uint32_t)(buf * GCA_STG_B);
        const uint32_t bs_u = as_u + (uint32_t)(128 * PAF * 4);
#pragma unroll
        for (int i = 0; i < 4; i++) {
            const int row = ar0 + i * 32;
            const bool valid = (row0 + row) < M;
            const int rclamp = valid ? (row0 + row) : (M - 1);
            cp16(as_u + (uint32_t)(row * PAF + akq) * 4u,
                 A + (size_t)rclamp * lda + k0 + akq, valid);
        }
#pragma unroll
        for (int i = 0; i < 2; i++) {
            const int row = br0 + i * 64;
            cp16(bs_u + (uint32_t)(row * PBH + bhc) * 2u,
                 Bt + (size_t)(col0 + row) * K + k0 + bhc, true);
        }
    };

    auto compute = [&](int buf) {
        const float* as = (const float*)(dynsmem_c + buf * GCA_STG_B);
        const uint32_t bs_u = smem_u + (uint32_t)(buf * GCA_STG_B)
                            + (uint32_t)(128 * PAF * 4);
#pragma unroll
        for (int kk = 0; kk < BK; kk += 16) {
            uint32_t a[4][4], b[4][2];
#pragma unroll
            for (int mi = 0; mi < 4; mi++) {
                const int r_lo = m0w + mi * 16 + g;
                const float2 f0 = *(const float2*)&as[(r_lo    ) * PAF + kk + 2 * q    ];
                const float2 f1 = *(const float2*)&as[(r_lo + 8) * PAF + kk + 2 * q    ];
                const float2 f2 = *(const float2*)&as[(r_lo    ) * PAF + kk + 8 + 2 * q];
                const float2 f3 = *(const float2*)&as[(r_lo + 8) * PAF + kk + 8 + 2 * q];
                __half2 h0 = __floats2half2_rn(f0.x, f0.y);
                __half2 h1 = __floats2half2_rn(f1.x, f1.y);
                __half2 h2 = __floats2half2_rn(f2.x, f2.y);
                __half2 h3 = __floats2half2_rn(f3.x, f3.y);
                a[mi][0] = *(uint32_t*)&h0; a[mi][1] = *(uint32_t*)&h1;
                a[mi][2] = *(uint32_t*)&h2; a[mi][3] = *(uint32_t*)&h3;
            }
#pragma unroll
            for (int p = 0; p < 2; p++) {
                uint32_t r0, r1, r2, r3;
                // x4 over [n][k]: mats (n0..7,k), (n0..7,k+8) -> one ni pair at b_lm
                ldsm4(r0, r1, r2, r3, bs_u + (uint32_t)(b_lm + (p * 16 * PBH + kk) * 2));
                b[p * 2 + 0][0] = r0; b[p * 2 + 0][1] = r1;
                b[p * 2 + 1][0] = r2; b[p * 2 + 1][1] = r3;
            }
#pragma unroll
            for (int mi = 0; mi < 4; mi++)
#pragma unroll
                for (int ni = 0; ni < 4; ni++)
                    mma_f16(acc[mi][ni], a[mi], b[ni]);
        }
    };

    const int nk = K / BK;
#pragma unroll
    for (int s = 0; s < 2; s++) {
        if (s < nk) issue(s, s);
        asm volatile("cp.async.commit_group;\n");
    }
    for (int it = 0; it < nk; it++) {
        asm volatile("cp.async.wait_group 1;\n");
        __syncthreads();
        const int nxt = it + 2;
        if (nxt < nk) issue(nxt % 3, nxt);
        asm volatile("cp.async.commit_group;\n");
        compute(it % 3);
    }

#pragma unroll
    for (int mi = 0; mi < 4; mi++) {
        const int r0 = row0 + m0w + mi * 16 + g;
        const int r1 = r0 + 8;
#pragma unroll
        for (int ni = 0; ni < 4; ni++) {
            const int c = col0 + n0w + ni * 8 + q * 2;
            const float bx = bias ? bias[c] : 0.f;
            const float by = bias ? bias[c + 1] : 0.f;
#pragma unroll
            for (int half = 0; half < 2; half++) {
                const int r = half ? r1 : r0;
                if (r < M) {
                    float vx = fmaxf(acc[mi][ni][half * 2 + 0] + bx, 0.f);
                    float vy = fmaxf(acc[mi][ni][half * 2 + 1] + by, 0.f);
                    *(__half2*)(C + (size_t)r * ldc + c) = __floats2half2_rn(vx, vy);
                }
            }
        }
    }
}

// ---------------- SpMM + ReLU over fp16 h, fp16 out (4-way unroll) -----------
__device__ __forceinline__ void accum8(float* acc, uint4 v, float w) {
    float2 f0 = __half22float2(*(__half2*)&v.x);
    float2 f1 = __half22float2(*(__half2*)&v.y);
    float2 f2 = __half22float2(*(__half2*)&v.z);
    float2 f3 = __half22float2(*(__half2*)&v.w);
    acc[0] += w * f0.x; acc[1] += w * f0.y;
    acc[2] += w * f1.x; acc[3] += w * f1.y;
    acc[4] += w * f2.x; acc[5] += w * f2.y;
    acc[6] += w * f3.x; acc[7] += w * f3.y;
}

__global__ __launch_bounds__(256) void k_spmm_relu(const __half* __restrict__ h, int layer) {
    const int sub  = threadIdx.x >> 5;
    const int lane = threadIdx.x & 31;
    const int d    = blockIdx.x * 8 + sub;
    const int beg  = g_rowptr[d];
    const int end  = g_rowptr[d + 1];
    const uint4* h16 = (const uint4*)h;
    float acc[8] = {0.f, 0.f, 0.f, 0.f, 0.f, 0.f, 0.f, 0.f};

    int k = beg;
    for (; k + 4 <= end; k += 4) {
        const int   s0 = g_colidx[k    ], s1 = g_colidx[k + 1];
        const int   s2 = g_colidx[k + 2], s3 = g_colidx[k + 3];
        const float w0 = g_vals[k    ], w1 = g_vals[k + 1];
        const float w2 = g_vals[k + 2], w3 = g_vals[k + 3];
        uint4 v0 = h16[(size_t)s0 * 32 + lane];
        uint4 v1 = h16[(size_t)s1 * 32 + lane];
        uint4 v2 = h16[(size_t)s2 * 32 + lane];
        uint4 v3 = h16[(size_t)s3 * 32 + lane];
        accum8(acc, v0, w0);
        accum8(acc, v1, w1);
        accum8(acc, v2, w2);
        accum8(acc, v3, w3);
    }
    for (; k < end; k++) {
        accum8(acc, h16[(size_t)g_colidx[k] * 32 + lane], g_vals[k]);
    }

    __half2 o0 = __floats2half2_rn(fmaxf(acc[0], 0.f), fmaxf(acc[1], 0.f));
    __half2 o1 = __floats2half2_rn(fmaxf(acc[2], 0.f), fmaxf(acc[3], 0.f));
    __half2 o2 = __floats2half2_rn(fmaxf(acc[4], 0.f), fmaxf(acc[5], 0.f));
    __half2 o3 = __floats2half2_rn(fmaxf(acc[6], 0.f), fmaxf(acc[7], 0.f));
    uint4 v;
    v.x = *(uint32_t*)&o0; v.y = *(uint32_t*)&o1;
    v.z = *(uint32_t*)&o2; v.w = *(uint32_t*)&o3;
    *(uint4*)(g_layers + (size_t)d * (NL * NH) + layer * NH + lane * 8) = v;
}

// ---------------- Launch ----------------------------------------------------
extern "C" void kernel_launch(void* const* d_in, const int* in_sizes, int n_in,
                              void* d_out, int out_size)
{
    const float* x        = (const float*)d_in[0];
    const float* evo      = (const float*)d_in[1];
    const int*   esrc     = (const int*)  d_in[2];
    const int*   edst     = (const int*)  d_in[3];
    const float* ew       = (const float*)d_in[4];
    const float* conv_w   = (const float*)d_in[5];
    const float* fc0_w    = (const float*)d_in[6];
    const float* fc0_b    = (const float*)d_in[7];
    const float* fc1_w    = (const float*)d_in[8];
    const float* fc1_b    = (const float*)d_in[9];
    const float* fc2_w    = (const float*)d_in[10];
    const float* fc2_b    = (const float*)d_in[11];
    const float* fc3_w    = (const float*)d_in[12];
    const float* fc3_b    = (const float*)d_in[13];
    float* out = (float*)d_out;

    __half *p_local0, *p_h, *p_layers, *p_glob, *p_local2, *p_wth;
    cudaGetSymbolAddress((void**)&p_local0, g_local0);
    cudaGetSymbolAddress((void**)&p_h,      g_h);
    cudaGetSymbolAddress((void**)&p_layers, g_layers);
    cudaGetSymbolAddress((void**)&p_glob,   g_glob);
    cudaGetSymbolAddress((void**)&p_local2, g_local2);
    cudaGetSymbolAddress((void**)&p_wth,    g_wth);

    const __half* wth_fc0  = p_wth;              // [256][512]
    const __half* wth_conv = p_wth + 131072;     // [4][256][256]
    const __half* wth_fc1  = p_wth + 393216;     // [256][1024]
    const __half* wth_fc2  = p_wth + 655360;     // [256][1024]
    const __half* wth_fc3  = p_wth + 917504;     // [256][512]

    cudaFuncSetAttribute(h16gemm<false, false, true >,
                         cudaFuncAttributeMaxDynamicSharedMemorySize, G16_SMEM);
    cudaFuncSetAttribute(h16gemm<true,  false, true >,
                         cudaFuncAttributeMaxDynamicSharedMemorySize, G16_SMEM);
    cudaFuncSetAttribute(h16gemm<true,  true,  false>,
                         cudaFuncAttributeMaxDynamicSharedMemorySize, G16_SMEM);
    cudaFuncSetAttribute(h16gemm_cvtA,
                         cudaFuncAttributeMaxDynamicSharedMemorySize, GCA_SMEM);

    const dim3 gemm_grid(2, (N_NODES + 127) / 128);

    // (pos 0) weight transpose + fp16 round
    k_prep_w<<<4096, 256>>>(fc0_w, conv_w, fc1_w, fc2_w, fc3_w);
    // (pos 1) fc0: local0 = fp16(relu(x @ fc0 + b)), fp32 A direct
    h16gemm_cvtA<<<gemm_grid, 256, GCA_SMEM>>>(
        x, NFEAT, NFEAT, wth_fc0, fc0_b, p_local0, NH, N_NODES);
    // (pos 2)
    k_zero_counts<<<(N_NODES + 255) / 256, 256>>>();
    // (pos 3) conv0 dense transform  <-- ncu capture target
    h16gemm<false, false, true><<<gemm_grid, 256, G16_SMEM>>>(
        p_local0, NH, NH, nullptr, wth_conv, nullptr, p_h, NH, N_NODES);
    // CSR build
    k_hist<<<E_EDGES / 256, 256>>>(edst);
    k_scan<<<1, 1024>>>();
    k_scatter<<<E_EDGES / 256, 256>>>(esrc, edst, ew);
    // spmm layer 0
    k_spmm_relu<<<N_NODES / 8, 256>>>(p_h, 0);

    // conv layers 1..3
    for (int i = 1; i < NL; i++) {
        h16gemm<false, false, true><<<gemm_grid, 256, G16_SMEM>>>(
            p_layers + (size_t)(i - 1) * NH, NL * NH, NH,
            nullptr, wth_conv + (size_t)i * NH * NH, nullptr, p_h, NH, N_NODES);
        k_spmm_relu<<<N_NODES / 8, 256>>>(p_h, i);
    }

    // fc2: local2 = fp16(relu(layers @ fc2 + b))
    h16gemm<true, false, true><<<gemm_grid, 256, G16_SMEM>>>(
        p_layers, NL * NH, NL * NH, nullptr, wth_fc2, fc2_b, p_local2, NH, N_NODES);

    // fc1: glob = fp16(relu(evo @ fc1 + b)), fp32 A direct
    h16gemm_cvtA<<<gemm_grid, 256, GCA_SMEM>>>(
        evo, EVO, EVO, wth_fc1, fc1_b, p_glob, NH, N_NODES);

    // fc3 (fused concat): out = relu([glob | local2] @ fc3 + b), fp32 out
    h16gemm<true, true, false><<<gemm_grid, 256, G16_SMEM>>>(
        p_glob, NH, 2 * NH, p_local2, wth_fc3, fc3_b, out, NH, N_NODES);
}

// round 15
// speedup vs baseline: 1.0509x; 1.0509x over previous
#include <cuda_runtime.h>
#include <cuda_fp16.h>
#include <cstddef>
#include <cstdint>

// ---------------- Problem constants (fixed by the reference) ----------------
#define N_NODES 50000
#define E_EDGES 800000
#define NFEAT   512
#define NH      256
#define NL      4
#define EVO     1024

// ---------------- Device-global scratch (no allocations allowed) ------------
__device__ __half g_xh[(size_t)N_NODES * NFEAT];          // fp16 copy of x
__device__ __half g_evoh[(size_t)N_NODES * EVO];          // fp16 copy of evo
__device__ __half g_local0[(size_t)N_NODES * NH];         // relu(x @ fc0), fp16
__device__ __half g_h[(size_t)N_NODES * NH];              // conv dense transform, fp16
__device__ __half g_layers[(size_t)N_NODES * NL * NH];    // spmm outputs, fp16
__device__ __half g_glob[(size_t)N_NODES * NH];           // relu(evo @ fc1), fp16
__device__ __half g_local2[(size_t)N_NODES * NH];         // relu(layers @ fc2), fp16

// All weights fp16, pre-transposed W^T [256][K] (k contiguous):
//  fc0 @0 (256x512), conv @131072 (4x256x256), fc1 @393216 (256x1024),
//  fc2 @655360 (256x1024), fc3 @917504 (256x512)
__device__ __half g_wth[1048576];

__device__ int   g_counts[N_NODES];
__device__ int   g_rowptr[N_NODES + 1];
__device__ int   g_cursor[N_NODES];
__device__ int   g_colidx[E_EDGES];
__device__ float g_vals[E_EDGES];

// ---------------- Weight prep: transpose + round to fp16 ---------------------
__global__ __launch_bounds__(256) void k_prep_w(
    const float* __restrict__ fc0w, const float* __restrict__ convw,
    const float* __restrict__ fc1w, const float* __restrict__ fc2w,
    const float* __restrict__ fc3w)
{
    const int i = blockIdx.x * 256 + threadIdx.x;         // 4096 x 256 = 1048576
    float v;
    if (i < 131072)      { int n = i >> 9, k = i & 511;   v = fc0w[k * 256 + n]; }
    else if (i < 393216) { int j = i - 131072; int m = j >> 16; int r = j & 65535;
                           int n = r >> 8, k = r & 255;   v = convw[m * 65536 + k * 256 + n]; }
    else if (i < 655360) { int j = i - 393216; int n = j >> 10, k = j & 1023;
                           v = fc1w[k * 256 + n]; }
    else if (i < 917504) { int j = i - 655360; int n = j >> 10, k = j & 1023;
                           v = fc2w[k * 256 + n]; }
    else                 { int j = i - 917504; int n = j >> 9, k = j & 511;
                           v = fc3w[k * 256 + n]; }
    g_wth[i] = __float2half_rn(v);
}

// ---------------- fp32 -> fp16 bulk convert (float4 per thread) -------------
__global__ __launch_bounds__(256) void k_cvt(const float* __restrict__ src,
                                             __half* __restrict__ dst) {
    const size_t i = ((size_t)blockIdx.x * 256 + threadIdx.x) * 4;
    float4 v = *(const float4*)(src + i);
    __half2 a = __floats2half2_rn(v.x, v.y);
    __half2 b = __floats2half2_rn(v.z, v.w);
    uint2 o;
    o.x = *(uint32_t*)&a; o.y = *(uint32_t*)&b;
    *(uint2*)(dst + i) = o;
}

// ---------------- CSR build kernels ----------------------------------------
__global__ void k_zero_counts() {
    int i = blockIdx.x * blockDim.x + threadIdx.x;
    if (i < N_NODES) g_counts[i] = 0;
}

__global__ void k_hist(const int* __restrict__ dst) {
    int e = blockIdx.x * blockDim.x + threadIdx.x;
    if (e < E_EDGES) atomicAdd(&g_counts[dst[e]], 1);
}

__global__ void k_scan() {
    __shared__ int warp_sums[32];
    __shared__ int s_carry;
    const int t = threadIdx.x, lane = t & 31, wid = t >> 5;
    if (t == 0) s_carry = 0;
    __syncthreads();
    for (int base = 0; base < N_NODES; base += 1024) {
        const int i = base + t;
        const int v = (i < N_NODES) ? g_counts[i] : 0;
        int x = v;
#pragma unroll
        for (int d = 1; d < 32; d <<= 1) {
            int y = __shfl_up_sync(0xFFFFFFFFu, x, d);
            if (lane >= d) x += y;
        }
        if (lane == 31) warp_sums[wid] = x;
        __syncthreads();
        if (wid == 0) {
            int w = warp_sums[lane];
            int ws = w;
#pragma unroll
            for (int d = 1; d < 32; d <<= 1) {
                int y = __shfl_up_sync(0xFFFFFFFFu, ws, d);
                if (lane >= d) ws += y;
            }
            warp_sums[lane] = ws - w;
        }
        __syncthreads();
        const int ex = x - v + warp_sums[wid];
        const int carry = s_carry;
        if (i < N_NODES) {
            g_rowptr[i] = carry + ex;
            g_cursor[i] = carry + ex;
        }
        __syncthreads();
        if (t == 1023) s_carry = carry + ex + v;
        __syncthreads();
    }
    if (threadIdx.x == 0) g_rowptr[N_NODES] = s_carry;
}

__global__ void k_scatter(const int* __restrict__ src, const int* __restrict__ dst,
                          const float* __restrict__ w) {
    int e = blockIdx.x * blockDim.x + threadIdx.x;
    if (e < E_EDGES) {
        int d = dst[e];
        int pos = atomicAdd(&g_cursor[d], 1);
        g_colidx[pos] = src[e];
        g_vals[pos]   = w[e];
    }
}

// ---------------- common asm helpers ----------------------------------------
__device__ __forceinline__ void ldsm4(uint32_t& r0, uint32_t& r1, uint32_t& r2, uint32_t& r3,
                                      uint32_t addr) {
    asm volatile("ldmatrix.sync.aligned.m8n8.x4.shared.b16 {%0,%1,%2,%3}, [%4];"
                 : "=r"(r0), "=r"(r1), "=r"(r2), "=r"(r3) : "r"(addr));
}

__device__ __forceinline__ void cp16(uint32_t dst_s, const void* src, bool valid) {
    int sz = valid ? 16 : 0;
    asm volatile("cp.async.cg.shared.global [%0], [%1], 16, %2;\n"
                 :: "r"(dst_s), "l"(src), "r"(sz));
}

__device__ __forceinline__ void mma_f16(float* d, const uint32_t* a, const uint32_t* b) {
    asm volatile(
        "mma.sync.aligned.m16n8k16.row.col.f32.f16.f16.f32 "
        "{%0,%1,%2,%3}, {%4,%5,%6,%7}, {%8,%9}, {%0,%1,%2,%3};\n"
        : "+f"(d[0]), "+f"(d[1]), "+f"(d[2]), "+f"(d[3])
        : "r"(a[0]), "r"(a[1]), "r"(a[2]), "r"(a[3]), "r"(b[0]), "r"(b[1]));
}

// ============================================================================
// FP16 GEMM (fp16 A + fp16 B, mma.m16n8k16, fp32 accum), BK=64, 3 stages.
// A smem [m][k] stride 72 halves; B smem [n][k] stride 72 halves.
// ============================================================================
#define G16_BK 64
#define G16_PA 72                       // halves; 144B stride, conflict-free
#define G16_STG_H (128 * G16_PA * 2)    // halves per stage (A + B) = 18432
#define G16_SMEM (3 * G16_STG_H * 2)    // bytes = 110592

template <bool RELU, bool CONCAT, bool OUT_HALF>
__global__ __launch_bounds__(256, 2) void h16gemm(
    const __half* __restrict__ A, int lda, int K,
    const __half* __restrict__ A2,          // CONCAT: second A at k>=256 (lda=256)
    const __half* __restrict__ Bt,          // [256][K] fp16, k contiguous
    const float* __restrict__ bias,
    void* __restrict__ Cv, int ldc, int M)
{
    constexpr int PA = G16_PA, BK = G16_BK;
    extern __shared__ __half dynsmem_h[];

    const int t    = threadIdx.x;
    const int lane = t & 31;
    const int warp = t >> 5;
    const int row0 = blockIdx.y * 128;
    const int col0 = blockIdx.x * 128;
    const int m0w  = (warp & 1) * 64;
    const int n0w  = (warp >> 1) * 32;
    const int g    = lane >> 2;
    const int q    = lane & 3;

    const uint32_t smem_u = (uint32_t)__cvta_generic_to_shared(dynsmem_h);

    float acc[4][4][4];
#pragma unroll
    for (int mi = 0; mi < 4; mi++)
#pragma unroll
        for (int ni = 0; ni < 4; ni++)
#pragma unroll
            for (int r = 0; r < 4; r++) acc[mi][ni][r] = 0.f;

    const int lr0 = t >> 3;
    const int lhc = (t & 7) * 8;

    const int a_lm = ((m0w + (lane & 15)) * PA + (lane >> 4) * 8) * 2;
    const int b_row = n0w + (lane & 7) + ((lane >> 4) & 1) * 8;
    const int b_lm  = (b_row * PA + ((lane >> 3) & 1) * 8) * 2;

    auto issue = [&](int buf, int stage_idx) {
        const int k0 = stage_idx * BK;
        const uint32_t as_u = smem_u + (uint32_t)(buf * G16_STG_H) * 2u;
        const uint32_t bs_u = as_u + (uint32_t)(128 * PA) * 2u;
        const __half* Asel = A;
        int kbase = k0;
        if (CONCAT && k0 >= 256) { Asel = A2; kbase = k0 - 256; }
#pragma unroll
        for (int i = 0; i < 4; i++) {
            const int row = lr0 + i * 32;
            const bool valid = (row0 + row) < M;
            const int rclamp = valid ? (row0 + row) : (M - 1);
            cp16(as_u + (uint32_t)(row * PA + lhc) * 2u,
                 Asel + (size_t)rclamp * lda + kbase + lhc, valid);
        }
#pragma unroll
        for (int i = 0; i < 4; i++) {
            const int row = lr0 + i * 32;
            cp16(bs_u + (uint32_t)(row * PA + lhc) * 2u,
                 Bt + (size_t)(col0 + row) * K + k0 + lhc, true);
        }
    };

    auto compute = [&](int buf) {
        const uint32_t as_u = smem_u + (uint32_t)(buf * G16_STG_H) * 2u;
        const uint32_t bs_u = as_u + (uint32_t)(128 * PA) * 2u;
#pragma unroll
        for (int kk = 0; kk < BK; kk += 16) {
            uint32_t a[4][4], b[4][2];
#pragma unroll
            for (int mi = 0; mi < 4; mi++)
                ldsm4(a[mi][0], a[mi][1], a[mi][2], a[mi][3],
                      as_u + (uint32_t)(a_lm + (mi * 16 * PA + kk) * 2));
#pragma unroll
            for (int p = 0; p < 2; p++) {
                uint32_t r0, r1, r2, r3;
                ldsm4(r0, r1, r2, r3,
                      bs_u + (uint32_t)(b_lm + (p * 16 * PA + kk) * 2));
                b[p * 2 + 0][0] = r0; b[p * 2 + 0][1] = r1;
                b[p * 2 + 1][0] = r2; b[p * 2 + 1][1] = r3;
            }
#pragma unroll
            for (int mi = 0; mi < 4; mi++)
#pragma unroll
                for (int ni = 0; ni < 4; ni++)
                    mma_f16(acc[mi][ni], a[mi], b[ni]);
        }
    };

    const int nk = K / BK;
#pragma unroll
    for (int s = 0; s < 2; s++) {
        if (s < nk) issue(s, s);
        asm volatile("cp.async.commit_group;\n");
    }
    for (int it = 0; it < nk; it++) {
        asm volatile("cp.async.wait_group 1;\n");
        __syncthreads();
        const int nxt = it + 2;
        if (nxt < nk) issue(nxt % 3, nxt);
        asm volatile("cp.async.commit_group;\n");
        compute(it % 3);
    }

#pragma unroll
    for (int mi = 0; mi < 4; mi++) {
        const int r0 = row0 + m0w + mi * 16 + g;
        const int r1 = r0 + 8;
#pragma unroll
        for (int ni = 0; ni < 4; ni++) {
            const int c = col0 + n0w + ni * 8 + q * 2;
            const float bx = bias ? bias[c] : 0.f;
            const float by = bias ? bias[c + 1] : 0.f;
#pragma unroll
            for (int half = 0; half < 2; half++) {
                const int r = half ? r1 : r0;
                if (r < M) {
                    float vx = acc[mi][ni][half * 2 + 0] + bx;
                    float vy = acc[mi][ni][half * 2 + 1] + by;
                    if (RELU) { vx = fmaxf(vx, 0.f); vy = fmaxf(vy, 0.f); }
                    if (OUT_HALF) {
                        *(__half2*)((__half*)Cv + (size_t)r * ldc + c) =
                            __floats2half2_rn(vx, vy);
                    } else {
                        *(float2*)((float*)Cv + (size_t)r * ldc + c) =
                            make_float2(vx, vy);
                    }
                }
            }
        }
    }
}

// ---------------- SpMM + ReLU over fp16 h, fp16 out (4-way unroll) -----------
__device__ __forceinline__ void accum8(float* acc, uint4 v, float w) {
    float2 f0 = __half22float2(*(__half2*)&v.x);
    float2 f1 = __half22float2(*(__half2*)&v.y);
    float2 f2 = __half22float2(*(__half2*)&v.z);
    float2 f3 = __half22float2(*(__half2*)&v.w);
    acc[0] += w * f0.x; acc[1] += w * f0.y;
    acc[2] += w * f1.x; acc[3] += w * f1.y;
    acc[4] += w * f2.x; acc[5] += w * f2.y;
    acc[6] += w * f3.x; acc[7] += w * f3.y;
}

__global__ __launch_bounds__(256) void k_spmm_relu(const __half* __restrict__ h, int layer) {
    const int sub  = threadIdx.x >> 5;
    const int lane = threadIdx.x & 31;
    const int d    = blockIdx.x * 8 + sub;
    const int beg  = g_rowptr[d];
    const int end  = g_rowptr[d + 1];
    const uint4* h16 = (const uint4*)h;
    float acc[8] = {0.f, 0.f, 0.f, 0.f, 0.f, 0.f, 0.f, 0.f};

    int k = beg;
    for (; k + 4 <= end; k += 4) {
        const int   s0 = g_colidx[k    ], s1 = g_colidx[k + 1];
        const int   s2 = g_colidx[k + 2], s3 = g_colidx[k + 3];
        const float w0 = g_vals[k    ], w1 = g_vals[k + 1];
        const float w2 = g_vals[k + 2], w3 = g_vals[k + 3];
        uint4 v0 = h16[(size_t)s0 * 32 + lane];
        uint4 v1 = h16[(size_t)s1 * 32 + lane];
        uint4 v2 = h16[(size_t)s2 * 32 + lane];
        uint4 v3 = h16[(size_t)s3 * 32 + lane];
        accum8(acc, v0, w0);
        accum8(acc, v1, w1);
        accum8(acc, v2, w2);
        accum8(acc, v3, w3);
    }
    for (; k < end; k++) {
        accum8(acc, h16[(size_t)g_colidx[k] * 32 + lane], g_vals[k]);
    }

    __half2 o0 = __floats2half2_rn(fmaxf(acc[0], 0.f), fmaxf(acc[1], 0.f));
    __half2 o1 = __floats2half2_rn(fmaxf(acc[2], 0.f), fmaxf(acc[3], 0.f));
    __half2 o2 = __floats2half2_rn(fmaxf(acc[4], 0.f), fmaxf(acc[5], 0.f));
    __half2 o3 = __floats2half2_rn(fmaxf(acc[6], 0.f), fmaxf(acc[7], 0.f));
    uint4 v;
    v.x = *(uint32_t*)&o0; v.y = *(uint32_t*)&o1;
    v.z = *(uint32_t*)&o2; v.w = *(uint32_t*)&o3;
    *(uint4*)(g_layers + (size_t)d * (NL * NH) + layer * NH + lane * 8) = v;
}

// ---------------- Launch ----------------------------------------------------
extern "C" void kernel_launch(void* const* d_in, const int* in_sizes, int n_in,
                              void* d_out, int out_size)
{
    const float* x        = (const float*)d_in[0];
    const float* evo      = (const float*)d_in[1];
    const int*   esrc     = (const int*)  d_in[2];
    const int*   edst     = (const int*)  d_in[3];
    const float* ew       = (const float*)d_in[4];
    const float* conv_w   = (const float*)d_in[5];
    const float* fc0_w    = (const float*)d_in[6];
    const float* fc0_b    = (const float*)d_in[7];
    const float* fc1_w    = (const float*)d_in[8];
    const float* fc1_b    = (const float*)d_in[9];
    const float* fc2_w    = (const float*)d_in[10];
    const float* fc2_b    = (const float*)d_in[11];
    const float* fc3_w    = (const float*)d_in[12];
    const float* fc3_b    = (const float*)d_in[13];
    float* out = (float*)d_out;

    __half *p_xh, *p_evoh, *p_local0, *p_h, *p_layers, *p_glob, *p_local2, *p_wth;
    cudaGetSymbolAddress((void**)&p_xh,     g_xh);
    cudaGetSymbolAddress((void**)&p_evoh,   g_evoh);
    cudaGetSymbolAddress((void**)&p_local0, g_local0);
    cudaGetSymbolAddress((void**)&p_h,      g_h);
    cudaGetSymbolAddress((void**)&p_layers, g_layers);
    cudaGetSymbolAddress((void**)&p_glob,   g_glob);
    cudaGetSymbolAddress((void**)&p_local2, g_local2);
    cudaGetSymbolAddress((void**)&p_wth,    g_wth);

    const __half* wth_fc0  = p_wth;              // [256][512]
    const __half* wth_conv = p_wth + 131072;     // [4][256][256]
    const __half* wth_fc1  = p_wth + 393216;     // [256][1024]
    const __half* wth_fc2  = p_wth + 655360;     // [256][1024]
    const __half* wth_fc3  = p_wth + 917504;     // [256][512]

    cudaFuncSetAttribute(h16gemm<false, false, true >,
                         cudaFuncAttributeMaxDynamicSharedMemorySize, G16_SMEM);
    cudaFuncSetAttribute(h16gemm<true,  false, true >,
                         cudaFuncAttributeMaxDynamicSharedMemorySize, G16_SMEM);
    cudaFuncSetAttribute(h16gemm<true,  true,  false>,
                         cudaFuncAttributeMaxDynamicSharedMemorySize, G16_SMEM);

    const dim3 gemm_grid(2, (N_NODES + 127) / 128);

    // (pos 0) weight transpose + fp16 round
    k_prep_w<<<4096, 256>>>(fc0_w, conv_w, fc1_w, fc2_w, fc3_w);
    // (pos 1) x -> fp16  (25,600,000 / 4 / 256 = 25000 blocks)
    k_cvt<<<25000, 256>>>(x, p_xh);
    // (pos 2) fc0: local0 = fp16(relu(x_h @ fc0 + b))
    h16gemm<true, false, true><<<gemm_grid, 256, G16_SMEM>>>(
        p_xh, NFEAT, NFEAT, nullptr, wth_fc0, fc0_b, p_local0, NH, N_NODES);
    // (pos 3) conv0 dense transform  <-- ncu capture target
    h16gemm<false, false, true><<<gemm_grid, 256, G16_SMEM>>>(
        p_local0, NH, NH, nullptr, wth_conv, nullptr, p_h, NH, N_NODES);
    // CSR build
    k_zero_counts<<<(N_NODES + 255) / 256, 256>>>();
    k_hist<<<E_EDGES / 256, 256>>>(edst);
    k_scan<<<1, 1024>>>();
    k_scatter<<<E_EDGES / 256, 256>>>(esrc, edst, ew);
    // spmm layer 0
    k_spmm_relu<<<N_NODES / 8, 256>>>(p_h, 0);

    // conv layers 1..3
    for (int i = 1; i < NL; i++) {
        h16gemm<false, false, true><<<gemm_grid, 256, G16_SMEM>>>(
            p_layers + (size_t)(i - 1) * NH, NL * NH, NH,
            nullptr, wth_conv + (size_t)i * NH * NH, nullptr, p_h, NH, N_NODES);
        k_spmm_relu<<<N_NODES / 8, 256>>>(p_h, i);
    }

    // evo -> fp16  (51,200,000 / 4 / 256 = 50000 blocks)
    k_cvt<<<50000, 256>>>(evo, p_evoh);

    // fc2: local2 = fp16(relu(layers @ fc2 + b))
    h16gemm<true, false, true><<<gemm_grid, 256, G16_SMEM>>>(
        p_layers, NL * NH, NL * NH, nullptr, wth_fc2, fc2_b, p_local2, NH, N_NODES);

    // fc1: glob = fp16(relu(evo_h @ fc1 + b))
    h16gemm<true, false, true><<<gemm_grid, 256, G16_SMEM>>>(
        p_evoh, EVO, EVO, nullptr, wth_fc1, fc1_b, p_glob, NH, N_NODES);

    // fc3 (fused concat): out = relu([glob | local2] @ fc3 + b), fp32 out
    h16gemm<true, true, false><<<gemm_grid, 256, G16_SMEM>>>(
        p_glob, NH, 2 * NH, p_local2, wth_fc3, fc3_b, out, NH, N_NODES);
}